// round 17
// baseline (speedup 1.0000x reference)
#include <cuda_runtime.h>
#include <math.h>
#include <stdint.h>

#define NN 512
#define EMB 64
#define HID 128
#define G4 512   // 4*HID
#define IN2 128  // 2*EMB

#define SMEM_D 48           // W rows (d') resident in SMEM (must be even)
#define SMEM_M (SMEM_D / 2) // 24 m-pairs in smem
#define RREM_M (64 - SMEM_M) // 40 m-pairs in registers (160 regs)
// dynamic smem floats: sW2 + double-buffered h [2][64][8] + sg [4][512]
#define LSTM_SMEM_FLOATS (SMEM_D * G4 + 2 * 64 * 8 + 4 * G4)
#define LSTM_SMEM_BYTES (LSTM_SMEM_FLOATS * 4)

// ---- scratch (device globals; no allocations allowed) ----
__device__ float g_input_feat[NN * IN2];   // [node][128]
__device__ float g_ihc[NN * G4];           // x@W_ih^T + b_ih + b_hh per node
__device__ int   g_orders[NN * NN];        // [start][step]; -1 = not ready
__device__ float g_Wp2[HID * G4];          // [m][j][2]: (W^T[2m][j], W^T[2m+1][j])
__device__ float g_embed[NN * HID];        // mean LSTM output per sequence
__device__ float g_logits[4 * NN];

// packed fp32x2 FMA (Blackwell): acc = a*b + acc, lanewise IEEE fp32
#define FFMA2(acc, a, b) \
    asm("fma.rn.f32x2 %0, %1, %2, %0;" : "+l"(acc) : "l"(a), "l"(b))

__device__ __forceinline__ unsigned long long pk2(float lo, float hi) {
    float2 f = make_float2(lo, hi);
    return *(unsigned long long*)&f;
}

// producer/consumer handshake (cross-kernel, concurrent streams)
__device__ __forceinline__ void st_rel(int* p, int v) {
    asm volatile("st.release.gpu.global.s32 [%0], %1;" :: "l"(p), "r"(v)
                 : "memory");
}
__device__ __forceinline__ int ld_acq(const int* p) {
    int v;
    asm volatile("ld.acquire.gpu.global.s32 %0, [%1];" : "=r"(v) : "l"(p)
                 : "memory");
    return v;
}
__device__ __forceinline__ int poll_order(const int* p) {
    int v = ld_acq(p);
    while (v < 0) v = ld_acq(p);
    return v;
}

// ---------------- Threefry2x32 (JAX-compatible) ----------------
__device__ __forceinline__ uint32_t rotl32(uint32_t x, int d) {
    return (x << d) | (x >> (32 - d));
}

__device__ __forceinline__ void threefry(uint32_t k0, uint32_t k1,
                                         uint32_t& x0, uint32_t& x1) {
    uint32_t ks2 = k0 ^ k1 ^ 0x1BD11BDAu;
    x0 += k0; x1 += k1;
    x0 += x1; x1 = rotl32(x1, 13); x1 ^= x0;
    x0 += x1; x1 = rotl32(x1, 15); x1 ^= x0;
    x0 += x1; x1 = rotl32(x1, 26); x1 ^= x0;
    x0 += x1; x1 = rotl32(x1, 6);  x1 ^= x0;
    x0 += k1; x1 += ks2 + 1u;
    x0 += x1; x1 = rotl32(x1, 17); x1 ^= x0;
    x0 += x1; x1 = rotl32(x1, 29); x1 ^= x0;
    x0 += x1; x1 = rotl32(x1, 16); x1 ^= x0;
    x0 += x1; x1 = rotl32(x1, 24); x1 ^= x0;
    x0 += ks2; x1 += k0 + 2u;
    x0 += x1; x1 = rotl32(x1, 13); x1 ^= x0;
    x0 += x1; x1 = rotl32(x1, 15); x1 ^= x0;
    x0 += x1; x1 = rotl32(x1, 26); x1 ^= x0;
    x0 += x1; x1 = rotl32(x1, 6);  x1 ^= x0;
    x0 += k0; x1 += k1 + 3u;
    x0 += x1; x1 = rotl32(x1, 17); x1 ^= x0;
    x0 += x1; x1 = rotl32(x1, 29); x1 ^= x0;
    x0 += x1; x1 = rotl32(x1, 16); x1 ^= x0;
    x0 += x1; x1 = rotl32(x1, 24); x1 ^= x0;
    x0 += k1; x1 += ks2 + 4u;
    x0 += x1; x1 = rotl32(x1, 13); x1 ^= x0;
    x0 += x1; x1 = rotl32(x1, 15); x1 ^= x0;
    x0 += x1; x1 = rotl32(x1, 26); x1 ^= x0;
    x0 += x1; x1 = rotl32(x1, 6);  x1 ^= x0;
    x0 += ks2; x1 += k0 + 5u;
}

// fast activations (err ~1e-6; recurrence is contractive)
__device__ __forceinline__ float fsig(float x) {
    return __fdividef(1.0f, 1.0f + __expf(-x));
}
__device__ __forceinline__ float ftanh(float x) {
    return __fdividef(2.0f, 1.0f + __expf(-2.0f * x)) - 1.0f;
}
__device__ __forceinline__ float sigf(float x) {  // accurate (non-LSTM paths)
    return 1.0f / (1.0f + expf(-x));
}

// ---------------- Kernel I: poison g_orders (re-run each replay) ----------
__global__ void k_init() {
    int idx = (blockIdx.x * 256 + threadIdx.x) * 2;
    g_orders[idx] = -1;
    g_orders[idx + 1] = -1;
}

// ---------------- Kernel A: node_feat / neigh_feat + W repack --------------
__global__ void k_embed(const int* __restrict__ tags,
                        const float* __restrict__ adj,
                        const float* __restrict__ W_emb,
                        const float* __restrict__ b_emb,
                        const float* __restrict__ W_hh) {
    int i = blockIdx.x;
    int dd = threadIdx.x;  // 64
    __shared__ int stags[NN];
    for (int j = dd; j < NN; j += 64) stags[j] = tags[j];
    __syncthreads();
    float nf = W_emb[stags[i] * EMB + dd] + b_emb[dd];
    float acc = 0.f;
    const float* arow = adj + (size_t)i * NN;
    for (int j = 0; j < NN; j++) {
        if (arow[j] > 0.5f) acc += W_emb[stags[j] * EMB + dd];
    }
    g_input_feat[i * IN2 + dd] = nf;
    g_input_feat[i * IN2 + EMB + dd] = acc + b_emb[dd];

    // fused W repack: g_Wp2[m*1024 + j*2 + e] = W_hh[j*128 + 2m + e]
    int E0 = (i * 64 + dd) * 2;
#pragma unroll
    for (int c = 0; c < 2; c++) {
        int E = E0 + c;
        int m = E >> 10;
        int rem = E & 1023;
        int j = rem >> 1;
        int e = rem & 1;
        g_Wp2[E] = W_hh[j * 128 + 2 * m + e];
    }
}

// ---------------- Kernel C: per-node input-gate contribution ----------------
__global__ void k_ihc(const float* __restrict__ W_ih,
                      const float* __restrict__ b_ih,
                      const float* __restrict__ b_hh) {
    int node = blockIdx.x;
    int j = threadIdx.x;  // 512
    __shared__ float sx[IN2];
    if (j < IN2) sx[j] = g_input_feat[node * IN2 + j];
    __syncthreads();
    const float* wr = W_ih + j * IN2;
    float acc = 0.f;
#pragma unroll 8
    for (int d = 0; d < IN2; d++) acc += sx[d] * wr[d];
    g_ihc[node * G4 + j] = acc + b_ih[j] + b_hh[j];
}

// ---------------- Kernel D: greedy noisy random-walk orderings ----------------
// Warp-per-walk (R15, bit-exact math: partitionable threefry + exact candidate
// filter). NOW A STREAMED PRODUCER: each completed order entry is published
// with st.release.gpu so the concurrently-running k_lstm can consume it.
__device__ __forceinline__ float walk_noise1(uint32_t f1, uint32_t f2, int i) {
    const float scale = 0.1f - 0.01f;
    uint32_t a = 0u, b = (uint32_t)i;
    threefry(f1, f2, a, b);
    uint32_t bits = a ^ b;
    float u = __uint_as_float((bits >> 9) | 0x3f800000u) - 1.0f;
    return fmaxf(0.01f, __fadd_rn(__fmul_rn(u, scale), 0.01f));
}

__global__ void __launch_bounds__(32) k_orders(const float* __restrict__ adj) {
    int s = blockIdx.x;
    int lane = threadIdx.x;  // 32
    __shared__ uint32_t fi1[NN], fi2[NN];
    __shared__ float candv[NN];
    __shared__ short candi[NN];

    uint32_t k1 = 0u, k2 = (uint32_t)s;
    threefry(0u, 42u, k1, k2);  // split(key(42), 512)[s]
#pragma unroll
    for (int c = 0; c < 16; c++) {
        int t = lane + 32 * c;
        uint32_t f1 = 0u, f2 = (uint32_t)t;
        threefry(k1, k2, f1, f2);
        fi1[t] = f1; fi2[t] = f2;
    }
    unsigned mask = 0xFFFFu;
    if ((s >> 4) == lane) mask &= ~(1u << (s & 15));
    if (lane == 0) st_rel(&g_orders[s * NN], s);
    int cur = s;
    __syncwarp();

    for (int t = 0; t < NN - 1; t++) {
        const float* arow = adj + (size_t)cur * NN;
        const float4* ar4 = (const float4*)(arow + lane * 16);
        float4 v0 = ar4[0], v1 = ar4[1], v2 = ar4[2], v3 = ar4[3];
        float a[16] = {v0.x, v0.y, v0.z, v0.w, v1.x, v1.y, v1.z, v1.w,
                       v2.x, v2.y, v2.z, v2.w, v3.x, v3.y, v3.z, v3.w};

        float mx = -1e30f;
#pragma unroll
        for (int k = 0; k < 16; k++)
            if ((mask >> k) & 1) mx = fmaxf(mx, a[k]);
#pragma unroll
        for (int off = 16; off > 0; off >>= 1)
            mx = fmaxf(mx, __shfl_xor_sync(0xffffffffu, mx, off));
        float thr2 = mx - 0.09001f;

        unsigned cm = 0;
#pragma unroll
        for (int k = 0; k < 16; k++)
            if (((mask >> k) & 1) && a[k] >= thr2) cm |= (1u << k);
        int cnt = __popc(cm);

        int pre = cnt;
#pragma unroll
        for (int off = 1; off < 32; off <<= 1) {
            int o = __shfl_up_sync(0xffffffffu, pre, off);
            if (lane >= off) pre += o;
        }
        int basee = pre - cnt;
        int tot = __shfl_sync(0xffffffffu, pre, 31);

        {
            unsigned cmt = cm;
            int idx = basee;
            while (cmt) {
                int k = __ffs(cmt) - 1;
                cmt &= cmt - 1;
                candv[idx] = a[k];
                candi[idx] = (short)(lane * 16 + k);
                idx++;
            }
        }
        __syncwarp();

        uint32_t f1 = fi1[t], f2 = fi2[t];
        unsigned long long key = 0ull;
        for (int bb = 0; bb < tot; bb += 32) {
            int p = bb + lane;
            if (p < tot) {
                int i = candi[p];
                float vv = candv[p] + walk_noise1(f1, f2, i);
                unsigned long long kk =
                    (((unsigned long long)__float_as_uint(vv)) << 32) |
                    (unsigned long long)(unsigned)(NN - 1 - i);
                if (kk > key) key = kk;
            }
        }
#pragma unroll
        for (int off = 16; off > 0; off >>= 1) {
            unsigned long long o = __shfl_xor_sync(0xffffffffu, key, off);
            if (o > key) key = o;
        }
        int nxt = (NN - 1) - (int)(unsigned)(key & 0xffffffffu);
        if ((nxt >> 4) == lane) mask &= ~(1u << (nxt & 15));
        if (lane == 0) st_rel(&g_orders[s * NN + t + 1], nxt);
        cur = nxt;
        __syncwarp();
    }
}

// ---------------- Kernel E: LSTM — even/odd-partial FFMA2 (R11 measured-best)
// NOW A STREAMED CONSUMER: order entries are read with acquire-polls against
// the -1 poison; the producer runs concurrently on a forked stream and is
// always >= 2 steps ahead after warm-up, so polls normally hit first try.
__global__ void __launch_bounds__(256) k_lstm() {
    extern __shared__ float smem[];
    float* sW2 = smem;                     // [SMEM_M][512][2]
    float* sh2 = smem + SMEM_D * G4;       // [2][64][8]
    float* sg  = sh2 + 2 * 64 * 8;         // [4][512] gates

    int bb = blockIdx.x;     // 0..127
    int tid = threadIdx.x;   // 0..255
    int base = bb * 4;
    int j0 = tid * 2;

    // stage SMEM W
    {
        const float4* src = (const float4*)g_Wp2;
        float4* dst = (float4*)sW2;
        for (int i = tid; i < SMEM_D * G4 / 4; i += 256) dst[i] = src[i];
    }
    ulonglong2 wr[RREM_M];
#pragma unroll
    for (int r = 0; r < RREM_M; r++)
        wr[r] = *(const ulonglong2*)&g_Wp2[((SMEM_M + r) * 512 + j0) * 2];

    for (int i = tid; i < 2 * 64 * 8; i += 256) sh2[i] = 0.f;

    int dA = tid & 127, bA = tid >> 7, bB = bA + 2;
    float cA = 0.f, cB = 0.f, eA = 0.f, eB = 0.f;

    unsigned long long ihcv[4], tmp[4];
    int ndB[4];
    {
        int nd0[4];
#pragma unroll
        for (int b = 0; b < 4; b++)
            nd0[b] = poll_order(&g_orders[(base + b) * NN]);
#pragma unroll
        for (int b = 0; b < 4; b++)
            ihcv[b] = *(const unsigned long long*)&g_ihc[nd0[b] * G4 + j0];
#pragma unroll
        for (int b = 0; b < 4; b++)
            ndB[b] = poll_order(&g_orders[(base + b) * NN + 1]);
    }
    __syncthreads();

    int buf = 0;
    for (int t = 0; t < NN; t++) {
        // issue next-step prefetches FIRST (complete under the GEMV)
        if (t + 1 < NN) {
#pragma unroll
            for (int b = 0; b < 4; b++)
                tmp[b] = *(const unsigned long long*)&g_ihc[ndB[b] * G4 + j0];
        }
        if (t + 2 < NN) {
#pragma unroll
            for (int b = 0; b < 4; b++)
                ndB[b] = poll_order(&g_orders[(base + b) * NN + t + 2]);
        }

        unsigned long long a00, a01, a10, a11, a20, a21, a30, a31;
        {
            float2 v0 = *(float2*)&ihcv[0];
            float2 v1 = *(float2*)&ihcv[1];
            float2 v2 = *(float2*)&ihcv[2];
            float2 v3 = *(float2*)&ihcv[3];
            a00 = pk2(v0.x, 0.f); a01 = pk2(v0.y, 0.f);
            a10 = pk2(v1.x, 0.f); a11 = pk2(v1.y, 0.f);
            a20 = pk2(v2.x, 0.f); a21 = pk2(v2.y, 0.f);
            a30 = pk2(v3.x, 0.f); a31 = pk2(v3.y, 0.f);
        }

        const float* shb = sh2 + buf * (64 * 8);
#pragma unroll 6
        for (int m = 0; m < SMEM_M; m++) {
            ulonglong2 w = *(const ulonglong2*)&sW2[(m * 512 + j0) * 2];
            ulonglong2 hA = *(const ulonglong2*)&shb[m * 8];
            ulonglong2 hB = *(const ulonglong2*)&shb[m * 8 + 4];
            FFMA2(a00, hA.x, w.x); FFMA2(a01, hA.x, w.y);
            FFMA2(a10, hA.y, w.x); FFMA2(a11, hA.y, w.y);
            FFMA2(a20, hB.x, w.x); FFMA2(a21, hB.x, w.y);
            FFMA2(a30, hB.y, w.x); FFMA2(a31, hB.y, w.y);
        }
#pragma unroll
        for (int r = 0; r < RREM_M; r++) {
            int m = SMEM_M + r;
            ulonglong2 hA = *(const ulonglong2*)&shb[m * 8];
            ulonglong2 hB = *(const ulonglong2*)&shb[m * 8 + 4];
            FFMA2(a00, hA.x, wr[r].x); FFMA2(a01, hA.x, wr[r].y);
            FFMA2(a10, hA.y, wr[r].x); FFMA2(a11, hA.y, wr[r].y);
            FFMA2(a20, hB.x, wr[r].x); FFMA2(a21, hB.x, wr[r].y);
            FFMA2(a30, hB.y, wr[r].x); FFMA2(a31, hB.y, wr[r].y);
        }

        {
            float2 c00 = *(float2*)&a00, c01 = *(float2*)&a01;
            float2 c10 = *(float2*)&a10, c11 = *(float2*)&a11;
            float2 c20 = *(float2*)&a20, c21 = *(float2*)&a21;
            float2 c30 = *(float2*)&a30, c31 = *(float2*)&a31;
            *(float2*)&sg[0 * G4 + j0] = make_float2(c00.x + c00.y, c01.x + c01.y);
            *(float2*)&sg[1 * G4 + j0] = make_float2(c10.x + c10.y, c11.x + c11.y);
            *(float2*)&sg[2 * G4 + j0] = make_float2(c20.x + c20.y, c21.x + c21.y);
            *(float2*)&sg[3 * G4 + j0] = make_float2(c30.x + c30.y, c31.x + c31.y);
        }
        __syncthreads();

        float* shn = sh2 + (buf ^ 1) * (64 * 8);
        int hoff = (dA >> 1) * 8 + (dA & 1);
        {
            const float* sgb = sg + bA * G4;
            float gi = sgb[dA], gf = sgb[128 + dA];
            float gg = sgb[256 + dA], go = sgb[384 + dA];
            cA = fsig(gf) * cA + fsig(gi) * ftanh(gg);
            float h = fsig(go) * ftanh(cA);
            eA += h;
            shn[hoff + bA * 2] = h;
        }
        {
            const float* sgb = sg + bB * G4;
            float gi = sgb[dA], gf = sgb[128 + dA];
            float gg = sgb[256 + dA], go = sgb[384 + dA];
            cB = fsig(gf) * cB + fsig(gi) * ftanh(gg);
            float h = fsig(go) * ftanh(cB);
            eB += h;
            shn[hoff + bB * 2] = h;
        }
#pragma unroll
        for (int b = 0; b < 4; b++) ihcv[b] = tmp[b];
        __syncthreads();
        buf ^= 1;
    }
    g_embed[(base + bA) * HID + dA] = eA * (1.0f / 512.0f);
    g_embed[(base + bB) * HID + dA] = eB * (1.0f / 512.0f);
}

// ---------------- Kernel F: 4-head MLP -> logits ----------------
__global__ void k_mlp(const float* __restrict__ W1s,
                      const float* __restrict__ b1s,
                      const float* __restrict__ W2s,
                      const float* __restrict__ b2s) {
    int n = blockIdx.x;
    int h = threadIdx.x;  // 128
    __shared__ float se[HID];
    __shared__ float red[128];
    se[h] = g_embed[n * HID + h];
    __syncthreads();
    for (int k = 0; k < 4; k++) {
        const float* W1 = W1s + k * HID * HID;
        float acc = b1s[k * HID + h];
#pragma unroll 8
        for (int d = 0; d < HID; d++) acc += se[d] * W1[d * HID + h];
        float r = fmaxf(acc, 0.f) * W2s[k * HID + h];
        red[h] = r;
        __syncthreads();
        for (int off = 64; off > 0; off >>= 1) {
            if (h < off) red[h] += red[h + off];
            __syncthreads();
        }
        if (h == 0) g_logits[k * NN + n] = red[0] + b2s[k];
        __syncthreads();
    }
}

// ---------------- Kernel G: loss + ensemble output ----------------
__global__ void k_final(const int* __restrict__ label,
                        const float* __restrict__ var_raw,
                        float* __restrict__ out) {
    int n = threadIdx.x;  // 512
    __shared__ float cw[4];
    __shared__ float red[NN];
    if (n < 4) {
        float x = var_raw[n];
        cw[n] = (x > 0.f) ? (x + log1pf(expf(-x))) : log1pf(expf(x));
    }
    __syncthreads();
    if (n == 0) {
        float s = cw[0] + cw[1] + cw[2] + cw[3];
        cw[0] /= s; cw[1] /= s; cw[2] /= s; cw[3] /= s;
    }
    __syncthreads();
    float lab = (float)label[0];
    float y = 0.f, lsum = 0.f;
#pragma unroll
    for (int k = 0; k < 4; k++) {
        float L = g_logits[k * NN + n];
        float ls_pos = (L > 0.f) ? -log1pf(expf(-L)) : (L - log1pf(expf(L)));
        float ls_neg = (L < 0.f) ? -log1pf(expf(L)) : (-L - log1pf(expf(-L)));
        lsum += -(lab * ls_pos + (1.f - lab) * ls_neg);
        y += cw[k] * sigf(L);
    }
    red[n] = lsum;
    __syncthreads();
    for (int off = 256; off > 0; off >>= 1) {
        if (n < off) red[n] += red[n + off];
        __syncthreads();
    }
    if (n == 0) out[0] = red[0] * (1.0f / 512.0f);  // sum_k mean_n
    out[1 + n] = y;
}

// ---------------- launcher ----------------
extern "C" void kernel_launch(void* const* d_in, const int* in_sizes, int n_in,
                              void* d_out, int out_size) {
    const int*   tags    = (const int*)d_in[0];
    const float* adj     = (const float*)d_in[1];
    const int*   label   = (const int*)d_in[2];
    const float* W_emb   = (const float*)d_in[3];
    const float* b_emb   = (const float*)d_in[4];
    const float* W_ih    = (const float*)d_in[5];
    const float* W_hh    = (const float*)d_in[6];
    const float* b_ih    = (const float*)d_in[7];
    const float* b_hh    = (const float*)d_in[8];
    const float* W1s     = (const float*)d_in[9];
    const float* b1s     = (const float*)d_in[10];
    const float* W2s     = (const float*)d_in[11];
    const float* b2s     = (const float*)d_in[12];
    const float* var_raw = (const float*)d_in[13];
    float* out = (float*)d_out;

    cudaFuncSetAttribute(k_lstm, cudaFuncAttributeMaxDynamicSharedMemorySize,
                         LSTM_SMEM_BYTES);

    // fork a non-blocking stream so k_orders (producer) runs CONCURRENTLY
    // with k_embed/k_ihc/k_lstm (consumer polls g_orders with acquire loads).
    // kernel_launch runs only during the correctness call + capture call, so
    // the (unfreed) stream/events are a bounded, capture-legal resource.
    cudaStream_t s2;
    cudaStreamCreateWithFlags(&s2, cudaStreamNonBlocking);
    cudaEvent_t e1, e2;
    cudaEventCreateWithFlags(&e1, cudaEventDisableTiming);
    cudaEventCreateWithFlags(&e2, cudaEventDisableTiming);

    k_init<<<NN, 256>>>();                 // poison g_orders to -1 (replay-safe)
    cudaEventRecord(e1, 0);
    cudaStreamWaitEvent(s2, e1, 0);
    k_orders<<<NN, 32, 0, s2>>>(adj);      // producer on forked stream

    k_embed<<<NN, 64>>>(tags, adj, W_emb, b_emb, W_hh);
    k_ihc<<<NN, G4>>>(W_ih, b_ih, b_hh);
    k_lstm<<<NN / 4, 256, LSTM_SMEM_BYTES>>>();  // consumer, overlaps producer

    cudaEventRecord(e2, s2);
    cudaStreamWaitEvent(0, e2, 0);         // join before capture ends
    k_mlp<<<NN, 128>>>(W1s, b1s, W2s, b2s);
    k_final<<<1, NN>>>(label, var_raw, out);
    (void)in_sizes; (void)n_in; (void)out_size;
}